// round 15
// baseline (speedup 1.0000x reference)
#include <cuda_runtime.h>
#include <cuda_fp16.h>
#include <math.h>
#include <stdint.h>

#define T_TOK 1024
#define HID   2048
#define NE    32
#define TOPK  6
#define NGRP  8
#define TGRP  3
#define IR    1408
#define IS    2816
#define CAP   384
#define RSCALE 16.0f

#define STAGE_BYTES 24576          // A 16KB (fp16 hi|lo rows) + B 8KB (2 panels x 4KB)
#define NSTG 4
#define SMEM_DYN 98304             // 4 stages (96KB); epilogue reuses first 64KB
#define NT 512                     // 16 warps (4Mx4N), warp tile 32x32

// merged-grid decode constants (CTA tile 128x128)
#define GU_SH_CTAS ((IS / 64) * (T_TOK / 128))          // 352
#define GU_RT_CTAS ((IR / 64) * (NE * (CAP / 128)))     // 2112
#define DN_SH_CTAS ((HID / 128) * (T_TOK / 128))        // 128
#define DN_RT_CTAS ((HID / 128) * (NE * (CAP / 128)))   // 1536

// ---------------- scratch (device globals: allocation-free) ----------------
__device__ int   g_topk_idx[T_TOK * TOPK];
__device__ float g_topk_w  [T_TOK * TOPK];
__device__ int   g_cnt     [NE];
__device__ int   g_rowtok  [NE * CAP];
__device__ int   g_slot    [T_TOK * TOPK];
__device__ float g_y       [(size_t)NE * CAP * HID];
__device__ unsigned short g_x_hi  [(size_t)(T_TOK + 1) * HID];
__device__ unsigned short g_x_lo  [(size_t)(T_TOK + 1) * HID];
__device__ unsigned short g_act_hi [(size_t)NE * CAP * IR];
__device__ unsigned short g_act_lo [(size_t)NE * CAP * IR];
__device__ unsigned short g_sact_hi[(size_t)T_TOK * IS];
__device__ unsigned short g_sact_lo[(size_t)T_TOK * IS];

// ---------------- helpers ----------------
__device__ __forceinline__ uint32_t smem_u32(const void* p) {
    uint32_t a;
    asm("{ .reg .u64 t; cvta.to.shared.u64 t, %1; cvt.u32.u64 %0, t; }" : "=r"(a) : "l"(p));
    return a;
}
#define SWZ(o) ((uint32_t)(o) ^ ((((uint32_t)(o)) >> 3) & 0x70u))

#define CP_ASYNC16(dst, src) \
    asm volatile("cp.async.cg.shared.global [%0], [%1], 16;" :: "r"(dst), "l"(src))
#define CP_COMMIT() asm volatile("cp.async.commit_group;" ::: "memory")
#define CP_WAIT2()  asm volatile("cp.async.wait_group 2;" ::: "memory")
#define CP_WAIT1()  asm volatile("cp.async.wait_group 1;" ::: "memory")
#define CP_WAIT0()  asm volatile("cp.async.wait_group 0;" ::: "memory")

__device__ __forceinline__ void ldsm4(uint32_t* r, uint32_t a) {
    asm volatile("ldmatrix.sync.aligned.m8n8.x4.shared.b16 {%0,%1,%2,%3}, [%4];"
        : "=r"(r[0]), "=r"(r[1]), "=r"(r[2]), "=r"(r[3]) : "r"(a));
}
__device__ __forceinline__ void ldsm4t(uint32_t* r, uint32_t a) {
    asm volatile("ldmatrix.sync.aligned.m8n8.x4.trans.shared.b16 {%0,%1,%2,%3}, [%4];"
        : "=r"(r[0]), "=r"(r[1]), "=r"(r[2]), "=r"(r[3]) : "r"(a));
}
__device__ __forceinline__ void mma16816h(float* c, const uint32_t* a, const uint32_t* b) {
    asm volatile("mma.sync.aligned.m16n8k16.row.col.f32.f16.f16.f32 "
        "{%0,%1,%2,%3}, {%4,%5,%6,%7}, {%8,%9}, {%0,%1,%2,%3};"
        : "+f"(c[0]), "+f"(c[1]), "+f"(c[2]), "+f"(c[3])
        : "r"(a[0]), "r"(a[1]), "r"(a[2]), "r"(a[3]), "r"(b[0]), "r"(b[1]));
}

__device__ __forceinline__ void hsplit(float f, unsigned short& h, unsigned short& l) {
    __half hh = __float2half_rn(f);
    float fh = __half2float(hh);
    __half ll = __float2half_rn(f - fh);
    h = __half_as_ushort(hh);
    l = __half_as_ushort(ll);
}
__device__ __forceinline__ uint32_t pack2(unsigned short a, unsigned short b) {
    return (uint32_t)a | ((uint32_t)b << 16);
}
__device__ __forceinline__ void hsplit4(float4 v, uint2& h, uint2& l) {
    unsigned short h0,l0,h1,l1,h2,l2,h3,l3;
    hsplit(v.x,h0,l0); hsplit(v.y,h1,l1); hsplit(v.z,h2,l2); hsplit(v.w,h3,l3);
    h = make_uint2(pack2(h0,h1), pack2(h2,h3));
    l = make_uint2(pack2(l0,l1), pack2(l2,l3));
}
__device__ __forceinline__ uint2 hround4(float4 v) {
    return make_uint2(
        pack2(__half_as_ushort(__float2half_rn(v.x)), __half_as_ushort(__float2half_rn(v.y))),
        pack2(__half_as_ushort(__float2half_rn(v.z)), __half_as_ushort(__float2half_rn(v.w))));
}

// ---------------- X pre-convert: fp32 -> fp16 hi/lo ----------------
__global__ void k_convx(const float* __restrict__ x) {
    int i = blockIdx.x * 256 + threadIdx.x;
    float4 v = *(const float4*)(x + (size_t)i * 4);
    uint2 h, l; hsplit4(v, h, l);
    *(uint2*)(g_x_hi + (size_t)i * 4) = h;
    *(uint2*)(g_x_lo + (size_t)i * 4) = l;
}

// ---------------- gate + routing (validated) ----------------
__global__ void k_gate(const float* __restrict__ x, const float* __restrict__ gw) {
    int t = blockIdx.x;
    __shared__ float xs[HID];
    __shared__ float lg[NE];
    const float* xr = x + (size_t)t * HID;
    for (int i = threadIdx.x; i < HID; i += 256) xs[i] = xr[i];
    __syncthreads();
    int e = threadIdx.x >> 3, j = threadIdx.x & 7;
    const float* w = gw + (size_t)e * HID;
    float s = 0.f;
    for (int i = j * 4; i < HID; i += 32) {
        float4 xv = *(const float4*)(xs + i);
        float4 wv = *(const float4*)(w + i);
        s += xv.x * wv.x + xv.y * wv.y + xv.z * wv.z + xv.w * wv.w;
    }
    #pragma unroll
    for (int off = 4; off; off >>= 1) s += __shfl_down_sync(0xffffffffu, s, off, 8);
    if (j == 0) lg[e] = s;
    __syncthreads();
    if (threadIdx.x == 0) {
        float gsc[NGRP]; int keep[NGRP];
        #pragma unroll
        for (int g2 = 0; g2 < NGRP; g2++) {
            float m4 = fmaxf(fmaxf(lg[g2*4], lg[g2*4+1]), fmaxf(lg[g2*4+2], lg[g2*4+3]));
            gsc[g2] = m4; keep[g2] = 0;
        }
        for (int it = 0; it < TGRP; it++) {
            float best = -INFINITY; int bi = 0;
            for (int g2 = 0; g2 < NGRP; g2++)
                if (!keep[g2] && gsc[g2] > best) { best = gsc[g2]; bi = g2; }
            keep[bi] = 1;
        }
        float sc[NE]; float mx = -INFINITY;
        for (int e2 = 0; e2 < NE; e2++) {
            float v = keep[e2 >> 2] ? lg[e2] : 0.0f;
            sc[e2] = v; mx = fmaxf(mx, v);
        }
        float sum = 0.f;
        for (int e2 = 0; e2 < NE; e2++) { float p = expf(sc[e2] - mx); sc[e2] = p; sum += p; }
        unsigned taken = 0u;
        for (int it = 0; it < TOPK; it++) {
            float best = -1.f; int bi = 0;
            for (int e2 = 0; e2 < NE; e2++)
                if (!((taken >> e2) & 1u) && sc[e2] > best) { best = sc[e2]; bi = e2; }
            taken |= 1u << bi;
            g_topk_idx[t * TOPK + it] = bi;
            g_topk_w  [t * TOPK + it] = (best / sum) * RSCALE;
        }
    }
}

__global__ void k_dispatch() {
    int w = threadIdx.x >> 5, lane = threadIdx.x & 31;
    int count = 0;
    for (int base = 0; base < T_TOK * TOPK; base += 32) {
        int idx = g_topk_idx[base + lane];
        unsigned m = __ballot_sync(0xffffffffu, idx == w);
        if (idx == w) {
            int pos = count + __popc(m & ((1u << lane) - 1u));
            int s = -1;
            if (pos < CAP) { s = w * CAP + pos; g_rowtok[s] = (base + lane) / TOPK; }
            g_slot[base + lane] = s;
        }
        count += __popc(m);
    }
    if (lane == 0) g_cnt[w] = count;
}

// =======================================================================
// MMA core: CTA 128x128, 16 warps (4Mx4N), warp tile 32x32, K-chunk 32,
// fp16 2-product. Stage: A [128][128B hi|lo] (16KB); B @+16384: 2 x 4KB.
// =======================================================================
__device__ __forceinline__ void mma_chunk(uint32_t sbs, int wm, int wn, int lane,
                                          float c[2][4][4]) {
    uint32_t Bh = sbs + 16384u + (uint32_t)(wn >> 1) * 4096u;
    #pragma unroll
    for (int kk = 0; kk < 2; kk++) {
        uint32_t ah[2][4], al[2][4], bh[2][4];
        #pragma unroll
        for (int mi = 0; mi < 2; mi++) {
            uint32_t ro = (uint32_t)((wm * 32 + mi * 16 + (lane & 15)) * 128
                                     + kk * 32 + ((lane >> 4) * 16));
            ldsm4(ah[mi], sbs + SWZ(ro));
            ldsm4(al[mi], sbs + SWZ(ro + 64));
        }
        #pragma unroll
        for (int ng = 0; ng < 2; ng++) {
            uint32_t ro = (uint32_t)((kk * 16 + (lane & 15)) * 128
                                     + (wn & 1) * 64 + ng * 32 + ((lane >> 4) * 16));
            ldsm4t(bh[ng], Bh + SWZ(ro));
        }
        #pragma unroll
        for (int mi = 0; mi < 2; mi++)
            #pragma unroll
            for (int ni = 0; ni < 4; ni++) {
                const uint32_t* bhp = &bh[ni >> 1][(ni & 1) * 2];
                mma16816h(c[mi][ni], ah[mi], bhp);
                mma16816h(c[mi][ni], al[mi], bhp);
            }
    }
}

__device__ __forceinline__ void stage_accum(float* ep, int wm, int wn, int lane,
                                            float c[2][4][4]) {
    #pragma unroll
    for (int mi = 0; mi < 2; mi++)
        #pragma unroll
        for (int ni = 0; ni < 4; ni++) {
            int row = wm * 32 + mi * 16 + (lane >> 2);
            int col = wn * 32 + ni * 8 + ((lane & 3) << 1);
            ep[row * 128 + col]           = c[mi][ni][0];
            ep[row * 128 + col + 1]       = c[mi][ni][1];
            ep[(row + 8) * 128 + col]     = c[mi][ni][2];
            ep[(row + 8) * 128 + col + 1] = c[mi][ni][3];
        }
}

// =======================================================================
// merged gate_up GEMM (routed + shared) + fused SiLU -> fp16 hi/lo acts
// 4-stage: cp_a 2 ahead; B raw-LDG 2 ahead (regs), convert+STS 1 ahead.
// =======================================================================
__global__ void __launch_bounds__(NT, 1)
k_mma_gateup(const float* __restrict__ Wgu, const float* __restrict__ Wsgu)
{
    extern __shared__ char dsm[];
    __shared__ int rix_s[128];
    int bid = blockIdx.x;
    int routed, e, mt, bx, Ihalf, cap;
    const float* B;
    if (bid < GU_SH_CTAS) {
        routed = 0; Ihalf = IS; cap = T_TOK;
        bx = bid % (IS / 64); mt = bid / (IS / 64); e = 0;
        B = Wsgu;
    } else {
        bid -= GU_SH_CTAS;
        routed = 1; Ihalf = IR; cap = CAP;
        bx = bid % (IR / 64); int by = bid / (IR / 64);
        e = by / (CAP / 128); mt = by % (CAP / 128);
        B = Wgu + (size_t)e * HID * (2 * IR);
    }
    const int ldb = 2 * Ihalf;
    int tid = threadIdx.x, wid = tid >> 5, lane = tid & 31;
    int wm = wid & 3, wn = wid >> 2;
    int cb = bx * 64;
    int rows = routed ? min(g_cnt[e], cap) : cap;
    int m0 = mt * 128;
    if (m0 >= rows) return;

    if (tid < 128) {
        int gm = m0 + tid;
        rix_s[tid] = (gm < rows) ? (routed ? g_rowtok[e * CAP + gm] : gm) : -1;
    }
    __syncthreads();

    const int NCH = HID >> 5;

    float F[2][4][4];
    #pragma unroll
    for (int mi = 0; mi < 2; mi++)
        #pragma unroll
        for (int ni = 0; ni < 4; ni++)
            #pragma unroll
            for (int q = 0; q < 4; q++) F[mi][ni][q] = 0.f;

    int arow = tid >> 2, aq = tid & 3;
    int bkr = tid >> 4, bn4 = tid & 15;
    int rt = rix_s[arow];
    size_t xrow = (size_t)(rt >= 0 ? rt : T_TOK) * HID;
    float4 bv[2][2];                      // [set][panel] raw fp32 B

    auto cp_a = [&](int c) {
        char* stg = dsm + (c % NSTG) * STAGE_BYTES;
        uint32_t sb = smem_u32(stg);
        size_t off = xrow + (c << 5) + aq * 8;
        CP_ASYNC16(sb + SWZ(arow * 128 + aq * 16),      g_x_hi + off);
        CP_ASYNC16(sb + SWZ(arow * 128 + 64 + aq * 16), g_x_lo + off);
        CP_COMMIT();
    };
    auto ldg_b = [&](int c, int set) {
        int k0 = c << 5;
        #pragma unroll
        for (int h = 0; h < 2; h++)
            bv[set][h] = *(const float4*)(B + (size_t)(k0 + bkr) * ldb + h * Ihalf + cb + bn4 * 4);
    };
    auto sts_b = [&](int c, int set) {    // convert happens here, 1 chunk after LDG
        char* stg = dsm + (c % NSTG) * STAGE_BYTES;
        #pragma unroll
        for (int h = 0; h < 2; h++) {
            uint2 h2 = hround4(bv[set][h]);
            char* bb = stg + 16384 + h * 4096;
            *(uint2*)(bb + SWZ(bkr * 128 + bn4 * 8)) = h2;
        }
    };

    // prologue: A0,A1 in flight; B0 staged; B1 raw in regs (set 1)
    cp_a(0); ldg_b(0, 0);
    cp_a(1); ldg_b(1, 1);
    sts_b(0, 0);

    for (int c = 0; c < NCH; c++) {
        if (c + 2 < NCH) { cp_a(c + 2); ldg_b(c + 2, c & 1); CP_WAIT2(); }
        else if (c + 1 < NCH) CP_WAIT1();
        else CP_WAIT0();
        __syncthreads();
        if (c + 1 < NCH) sts_b(c + 1, (c + 1) & 1);
        mma_chunk(smem_u32(dsm + (c % NSTG) * STAGE_BYTES), wm, wn, lane, F);
    }
    __syncthreads();

    // ---- epilogue: accum -> smem fp32, silu(g)*u -> fp16 hi/lo -> gmem
    float* ep = (float*)dsm;
    stage_accum(ep, wm, wn, lane, F);
    __syncthreads();

    int m = tid >> 2, seg = tid & 3;
    int rg = m0 + m;
    if (rg < rows) {
        unsigned short* Oh = routed ? g_act_hi : g_sact_hi;
        unsigned short* Ol = routed ? g_act_lo : g_sact_lo;
        size_t rowoff = ((size_t)(routed ? e * CAP : 0) + rg) * Ihalf + cb + seg * 16;
        const float* gp = ep + m * 128 + seg * 16;
        const float* up = gp + 64;
        uint32_t hi[8], lo[8];
        #pragma unroll
        for (int j = 0; j < 8; j++) {
            float g0 = gp[2*j],   u0 = up[2*j];
            float g1 = gp[2*j+1], u1 = up[2*j+1];
            float s0 = u0 * g0 / (1.f + expf(-g0));
            float s1 = u1 * g1 / (1.f + expf(-g1));
            unsigned short h0, l0, h1, l1;
            hsplit(s0, h0, l0); hsplit(s1, h1, l1);
            hi[j] = pack2(h0, h1); lo[j] = pack2(l0, l1);
        }
        #pragma unroll
        for (int j = 0; j < 2; j++) {
            *(uint4*)(Oh + rowoff + j * 8) = *(uint4*)(hi + j * 4);
            *(uint4*)(Ol + rowoff + j * 8) = *(uint4*)(lo + j * 4);
        }
    }
}

// =======================================================================
// merged down GEMM: act fp16 hi/lo via cp.async @ W(fp16-rounded) -> fp32
// =======================================================================
__global__ void __launch_bounds__(NT, 1)
k_mma_down(const float* __restrict__ Wd, const float* __restrict__ Wsd,
           float* __restrict__ Oext)
{
    extern __shared__ char dsm[];
    int bid = blockIdx.x;
    int routed, e, mt, bx, Kdim, cap;
    const float* B;
    if (bid < DN_SH_CTAS) {
        routed = 0; Kdim = IS; cap = T_TOK;
        bx = bid % (HID / 128); mt = bid / (HID / 128); e = 0;
        B = Wsd;
    } else {
        bid -= DN_SH_CTAS;
        routed = 1; Kdim = IR; cap = CAP;
        bx = bid % (HID / 128); int by = bid / (HID / 128);
        e = by / (CAP / 128); mt = by % (CAP / 128);
        B = Wd + (size_t)e * IR * HID;
    }
    int tid = threadIdx.x, wid = tid >> 5, lane = tid & 31;
    int wm = wid & 3, wn = wid >> 2;
    int n0 = bx * 128;
    int rows = routed ? min(g_cnt[e], cap) : cap;
    int m0 = mt * 128;
    if (m0 >= rows) return;

    const unsigned short* Ah = routed ? g_act_hi : g_sact_hi;
    const unsigned short* Al = routed ? g_act_lo : g_sact_lo;
    size_t abase = ((size_t)(routed ? e * CAP : 0) + m0) * Kdim;
    const int NCH = Kdim >> 5;

    float F[2][4][4];
    #pragma unroll
    for (int mi = 0; mi < 2; mi++)
        #pragma unroll
        for (int ni = 0; ni < 4; ni++)
            #pragma unroll
            for (int q = 0; q < 4; q++) F[mi][ni][q] = 0.f;

    int arow = tid >> 2, aq = tid & 3;
    int bkr = tid >> 4, bn4 = tid & 15;
    float4 bv[2][2];

    auto cp_a = [&](int c) {
        char* stg = dsm + (c % NSTG) * STAGE_BYTES;
        int k0 = c << 5;
        uint32_t sb = smem_u32(stg);
        size_t off = abase + (size_t)arow * Kdim + k0 + aq * 8;
        CP_ASYNC16(sb + SWZ(arow * 128 + aq * 16),      Ah + off);
        CP_ASYNC16(sb + SWZ(arow * 128 + 64 + aq * 16), Al + off);
        CP_COMMIT();
    };
    auto ldg_b = [&](int c, int set) {
        int k0 = c << 5;
        #pragma unroll
        for (int h = 0; h < 2; h++)
            bv[set][h] = *(const float4*)(B + (size_t)(k0 + bkr) * HID + n0 + h * 64 + bn4 * 4);
    };
    auto sts_b = [&](int c, int set) {
        char* stg = dsm + (c % NSTG) * STAGE_BYTES;
        #pragma unroll
        for (int h = 0; h < 2; h++) {
            uint2 h2 = hround4(bv[set][h]);
            char* bb = stg + 16384 + h * 4096;
            *(uint2*)(bb + SWZ(bkr * 128 + bn4 * 8)) = h2;
        }
    };

    cp_a(0); ldg_b(0, 0);
    cp_a(1); ldg_b(1, 1);
    sts_b(0, 0);

    for (int c = 0; c < NCH; c++) {
        if (c + 2 < NCH) { cp_a(c + 2); ldg_b(c + 2, c & 1); CP_WAIT2(); }
        else if (c + 1 < NCH) CP_WAIT1();
        else CP_WAIT0();
        __syncthreads();
        if (c + 1 < NCH) sts_b(c + 1, (c + 1) & 1);
        mma_chunk(smem_u32(dsm + (c % NSTG) * STAGE_BYTES), wm, wn, lane, F);
    }
    __syncthreads();

    float* ep = (float*)dsm;
    stage_accum(ep, wm, wn, lane, F);
    __syncthreads();

    int m = tid >> 2, cs = (tid & 3) << 5;
    int rg = m0 + m;
    if (rg < rows) {
        float* O = routed ? g_y : Oext;
        float* op = O + ((size_t)(routed ? e * CAP : 0) + rg) * HID + n0 + cs;
        const float* sp = ep + m * 128 + cs;
        #pragma unroll
        for (int j = 0; j < 8; j++)
            *(float4*)(op + j * 4) = *(const float4*)(sp + j * 4);
    }
}

// ---------------- combine ----------------
__global__ void k_combine(float* __restrict__ out) {
    int idx = blockIdx.x * 256 + threadIdx.x;
    int t = idx >> 9;
    int h = (idx & 511) << 2;
    float* op = out + (size_t)t * HID + h;
    float4 acc = *(float4*)op;
    #pragma unroll
    for (int k = 0; k < TOPK; k++) {
        int s = g_slot[t * TOPK + k];
        if (s >= 0) {
            float wv = g_topk_w[t * TOPK + k];
            float4 y = *(const float4*)(g_y + (size_t)s * HID + h);
            acc.x += wv * y.x; acc.y += wv * y.y; acc.z += wv * y.z; acc.w += wv * y.w;
        }
    }
    *(float4*)op = acc;
}

// ---------------- entry ----------------
extern "C" void kernel_launch(void* const* d_in, const int* in_sizes, int n_in,
                              void* d_out, int out_size) {
    const float* x    = (const float*)d_in[0];
    const float* gw   = (const float*)d_in[1];
    const float* wgu  = (const float*)d_in[2];
    const float* wd   = (const float*)d_in[3];
    const float* wsgu = (const float*)d_in[4];
    const float* wsd  = (const float*)d_in[5];
    float* out = (float*)d_out;

    cudaFuncSetAttribute(k_mma_gateup, cudaFuncAttributeMaxDynamicSharedMemorySize, SMEM_DYN);
    cudaFuncSetAttribute(k_mma_down,   cudaFuncAttributeMaxDynamicSharedMemorySize, SMEM_DYN);

    k_convx   <<<(T_TOK * HID / 4) / 256, 256>>>(x);
    k_gate    <<<T_TOK, 256>>>(x, gw);
    k_dispatch<<<1, 1024>>>();
    k_mma_gateup<<<GU_SH_CTAS + GU_RT_CTAS, NT, SMEM_DYN>>>(wgu, wsgu);
    k_mma_down  <<<DN_SH_CTAS + DN_RT_CTAS, NT, SMEM_DYN>>>(wd, wsd, out);
    k_combine <<<(T_TOK * HID / 4) / 256, 256>>>(out);
}

// round 16
// speedup vs baseline: 1.5553x; 1.5553x over previous
#include <cuda_runtime.h>
#include <cuda_fp16.h>
#include <math.h>
#include <stdint.h>

#define T_TOK 1024
#define HID   2048
#define NE    32
#define TOPK  6
#define NGRP  8
#define TGRP  3
#define IR    1408
#define IS    2816
#define CAP   384
#define RSCALE 16.0f

#define STAGE_BYTES 32768          // A 16KB (fp16, 64K-elems/row) + B 16KB (2 panels x 8KB)
#define SMEM_DYN    65536          // 2 stages; epilogue reuses as 128x128 fp32
#define NT 512                     // 16 warps (4Mx4N), warp tile 32x32, K-chunk 64

// merged-grid decode constants (CTA tile 128x128)
#define GU_SH_CTAS ((IS / 64) * (T_TOK / 128))          // 352
#define GU_RT_CTAS ((IR / 64) * (NE * (CAP / 128)))     // 2112
#define DN_SH_CTAS ((HID / 128) * (T_TOK / 128))        // 128
#define DN_RT_CTAS ((HID / 128) * (NE * (CAP / 128)))   // 1536

// ---------------- scratch (device globals: allocation-free) ----------------
__device__ int   g_topk_idx[T_TOK * TOPK];
__device__ float g_topk_w  [T_TOK * TOPK];
__device__ int   g_cnt     [NE];
__device__ int   g_rowtok  [NE * CAP];
__device__ int   g_slot    [T_TOK * TOPK];
__device__ float g_y       [(size_t)NE * CAP * HID];
__device__ unsigned short g_x16  [(size_t)(T_TOK + 1) * HID];   // fp16 X (+1 zero row)
__device__ unsigned short g_act16 [(size_t)NE * CAP * IR];      // fp16 routed acts
__device__ unsigned short g_sact16[(size_t)T_TOK * IS];         // fp16 shared acts

// ---------------- helpers ----------------
__device__ __forceinline__ uint32_t smem_u32(const void* p) {
    uint32_t a;
    asm("{ .reg .u64 t; cvta.to.shared.u64 t, %1; cvt.u32.u64 %0, t; }" : "=r"(a) : "l"(p));
    return a;
}
#define SWZ(o) ((uint32_t)(o) ^ ((((uint32_t)(o)) >> 3) & 0x70u))

#define CP_ASYNC16(dst, src) \
    asm volatile("cp.async.cg.shared.global [%0], [%1], 16;" :: "r"(dst), "l"(src))
#define CP_COMMIT() asm volatile("cp.async.commit_group;" ::: "memory")
#define CP_WAIT0()  asm volatile("cp.async.wait_group 0;" ::: "memory")

__device__ __forceinline__ void ldsm4(uint32_t* r, uint32_t a) {
    asm volatile("ldmatrix.sync.aligned.m8n8.x4.shared.b16 {%0,%1,%2,%3}, [%4];"
        : "=r"(r[0]), "=r"(r[1]), "=r"(r[2]), "=r"(r[3]) : "r"(a));
}
__device__ __forceinline__ void ldsm4t(uint32_t* r, uint32_t a) {
    asm volatile("ldmatrix.sync.aligned.m8n8.x4.trans.shared.b16 {%0,%1,%2,%3}, [%4];"
        : "=r"(r[0]), "=r"(r[1]), "=r"(r[2]), "=r"(r[3]) : "r"(a));
}
__device__ __forceinline__ void mma16816h(float* c, const uint32_t* a, const uint32_t* b) {
    asm volatile("mma.sync.aligned.m16n8k16.row.col.f32.f16.f16.f32 "
        "{%0,%1,%2,%3}, {%4,%5,%6,%7}, {%8,%9}, {%0,%1,%2,%3};"
        : "+f"(c[0]), "+f"(c[1]), "+f"(c[2]), "+f"(c[3])
        : "r"(a[0]), "r"(a[1]), "r"(a[2]), "r"(a[3]), "r"(b[0]), "r"(b[1]));
}

__device__ __forceinline__ uint32_t pack2(unsigned short a, unsigned short b) {
    return (uint32_t)a | ((uint32_t)b << 16);
}
__device__ __forceinline__ uint2 hround4(float4 v) {
    return make_uint2(
        pack2(__half_as_ushort(__float2half_rn(v.x)), __half_as_ushort(__float2half_rn(v.y))),
        pack2(__half_as_ushort(__float2half_rn(v.z)), __half_as_ushort(__float2half_rn(v.w))));
}

// ---------------- X pre-convert: fp32 -> fp16 (once) ----------------
__global__ void k_convx(const float* __restrict__ x) {
    int i = blockIdx.x * 256 + threadIdx.x;
    float4 v = *(const float4*)(x + (size_t)i * 4);
    *(uint2*)(g_x16 + (size_t)i * 4) = hround4(v);
}

// ---------------- gate + routing (validated) ----------------
__global__ void k_gate(const float* __restrict__ x, const float* __restrict__ gw) {
    int t = blockIdx.x;
    __shared__ float xs[HID];
    __shared__ float lg[NE];
    const float* xr = x + (size_t)t * HID;
    for (int i = threadIdx.x; i < HID; i += 256) xs[i] = xr[i];
    __syncthreads();
    int e = threadIdx.x >> 3, j = threadIdx.x & 7;
    const float* w = gw + (size_t)e * HID;
    float s = 0.f;
    for (int i = j * 4; i < HID; i += 32) {
        float4 xv = *(const float4*)(xs + i);
        float4 wv = *(const float4*)(w + i);
        s += xv.x * wv.x + xv.y * wv.y + xv.z * wv.z + xv.w * wv.w;
    }
    #pragma unroll
    for (int off = 4; off; off >>= 1) s += __shfl_down_sync(0xffffffffu, s, off, 8);
    if (j == 0) lg[e] = s;
    __syncthreads();
    if (threadIdx.x == 0) {
        float gsc[NGRP]; int keep[NGRP];
        #pragma unroll
        for (int g2 = 0; g2 < NGRP; g2++) {
            float m4 = fmaxf(fmaxf(lg[g2*4], lg[g2*4+1]), fmaxf(lg[g2*4+2], lg[g2*4+3]));
            gsc[g2] = m4; keep[g2] = 0;
        }
        for (int it = 0; it < TGRP; it++) {
            float best = -INFINITY; int bi = 0;
            for (int g2 = 0; g2 < NGRP; g2++)
                if (!keep[g2] && gsc[g2] > best) { best = gsc[g2]; bi = g2; }
            keep[bi] = 1;
        }
        float sc[NE]; float mx = -INFINITY;
        for (int e2 = 0; e2 < NE; e2++) {
            float v = keep[e2 >> 2] ? lg[e2] : 0.0f;
            sc[e2] = v; mx = fmaxf(mx, v);
        }
        float sum = 0.f;
        for (int e2 = 0; e2 < NE; e2++) { float p = expf(sc[e2] - mx); sc[e2] = p; sum += p; }
        unsigned taken = 0u;
        for (int it = 0; it < TOPK; it++) {
            float best = -1.f; int bi = 0;
            for (int e2 = 0; e2 < NE; e2++)
                if (!((taken >> e2) & 1u) && sc[e2] > best) { best = sc[e2]; bi = e2; }
            taken |= 1u << bi;
            g_topk_idx[t * TOPK + it] = bi;
            g_topk_w  [t * TOPK + it] = (best / sum) * RSCALE;
        }
    }
}

__global__ void k_dispatch() {
    int w = threadIdx.x >> 5, lane = threadIdx.x & 31;
    int count = 0;
    for (int base = 0; base < T_TOK * TOPK; base += 32) {
        int idx = g_topk_idx[base + lane];
        unsigned m = __ballot_sync(0xffffffffu, idx == w);
        if (idx == w) {
            int pos = count + __popc(m & ((1u << lane) - 1u));
            int s = -1;
            if (pos < CAP) { s = w * CAP + pos; g_rowtok[s] = (base + lane) / TOPK; }
            g_slot[base + lane] = s;
        }
        count += __popc(m);
    }
    if (lane == 0) g_cnt[w] = count;
}

// =======================================================================
// MMA core: CTA 128x128, 16 warps (4Mx4N), warp tile 32x32, K-chunk 64,
// single-fp16 product.
// Stage: A [128 rows][128B = 64 fp16] @0 (16KB);
//        B @+16384: panel p {64 cols}: [64 krows][128B] 8KB @p*8192.
// =======================================================================
__device__ __forceinline__ void mma_chunk(uint32_t sbs, int wm, int wn, int lane,
                                          float c[2][4][4]) {
    uint32_t Bh = sbs + 16384u + (uint32_t)(wn >> 1) * 8192u;
    #pragma unroll
    for (int kk = 0; kk < 4; kk++) {
        uint32_t ah[2][4], bh[2][4];
        #pragma unroll
        for (int mi = 0; mi < 2; mi++) {
            uint32_t ro = (uint32_t)((wm * 32 + mi * 16 + (lane & 15)) * 128
                                     + kk * 32 + ((lane >> 4) * 16));
            ldsm4(ah[mi], sbs + SWZ(ro));
        }
        #pragma unroll
        for (int ng = 0; ng < 2; ng++) {
            uint32_t ro = (uint32_t)((kk * 16 + (lane & 15)) * 128
                                     + (wn & 1) * 64 + ng * 32 + ((lane >> 4) * 16));
            ldsm4t(bh[ng], Bh + SWZ(ro));
        }
        #pragma unroll
        for (int mi = 0; mi < 2; mi++)
            #pragma unroll
            for (int ni = 0; ni < 4; ni++)
                mma16816h(c[mi][ni], ah[mi], &bh[ni >> 1][(ni & 1) * 2]);
    }
}

__device__ __forceinline__ void stage_accum(float* ep, int wm, int wn, int lane,
                                            float c[2][4][4]) {
    #pragma unroll
    for (int mi = 0; mi < 2; mi++)
        #pragma unroll
        for (int ni = 0; ni < 4; ni++) {
            int row = wm * 32 + mi * 16 + (lane >> 2);
            int col = wn * 32 + ni * 8 + ((lane & 3) << 1);
            ep[row * 128 + col]           = c[mi][ni][0];
            ep[row * 128 + col + 1]       = c[mi][ni][1];
            ep[(row + 8) * 128 + col]     = c[mi][ni][2];
            ep[(row + 8) * 128 + col + 1] = c[mi][ni][3];
        }
}

// =======================================================================
// merged gate_up GEMM (routed + shared) + fused SiLU -> fp16 acts
// R13 loop ordering: ldg(c+1) -> mma(c) -> sts(c+1) -> wait -> bar.
// =======================================================================
__global__ void __launch_bounds__(NT, 1)
k_mma_gateup(const float* __restrict__ Wgu, const float* __restrict__ Wsgu)
{
    extern __shared__ char dsm[];
    __shared__ int rix_s[128];
    int bid = blockIdx.x;
    int routed, e, mt, bx, Ihalf, cap;
    const float* B;
    if (bid < GU_SH_CTAS) {
        routed = 0; Ihalf = IS; cap = T_TOK;
        bx = bid % (IS / 64); mt = bid / (IS / 64); e = 0;
        B = Wsgu;
    } else {
        bid -= GU_SH_CTAS;
        routed = 1; Ihalf = IR; cap = CAP;
        bx = bid % (IR / 64); int by = bid / (IR / 64);
        e = by / (CAP / 128); mt = by % (CAP / 128);
        B = Wgu + (size_t)e * HID * (2 * IR);
    }
    const int ldb = 2 * Ihalf;
    int tid = threadIdx.x, wid = tid >> 5, lane = tid & 31;
    int wm = wid & 3, wn = wid >> 2;
    int cb = bx * 64;
    int rows = routed ? min(g_cnt[e], cap) : cap;
    int m0 = mt * 128;
    if (m0 >= rows) return;

    if (tid < 128) {
        int gm = m0 + tid;
        rix_s[tid] = (gm < rows) ? (routed ? g_rowtok[e * CAP + gm] : gm) : -1;
    }
    __syncthreads();

    const int NCH = HID >> 6;

    float F[2][4][4];
    #pragma unroll
    for (int mi = 0; mi < 2; mi++)
        #pragma unroll
        for (int ni = 0; ni < 4; ni++)
            #pragma unroll
            for (int q = 0; q < 4; q++) F[mi][ni][q] = 0.f;

    int arow = tid >> 2, aq = tid & 3;            // A: 4 thr/row, 16 fp16 each
    int bkr = tid >> 3, bq = tid & 7;             // B: 8 thr/krow, 16 fp32 each
    int rt = rix_s[arow];
    size_t xrow = (size_t)(rt >= 0 ? rt : T_TOK) * HID;
    int srccol = (bq < 4) ? (cb + bq * 16) : (Ihalf + cb + (bq - 4) * 16);
    float4 bv[4];

    auto cp_a = [&](int c) {
        char* stg = dsm + (c & 1) * STAGE_BYTES;
        uint32_t sb = smem_u32(stg);
        size_t off = xrow + (c << 6) + aq * 16;
        uint32_t o = arow * 128 + aq * 32;
        CP_ASYNC16(sb + SWZ(o),      g_x16 + off);
        CP_ASYNC16(sb + SWZ(o + 16), g_x16 + off + 8);
        CP_COMMIT();
    };
    auto ldg_b = [&](int c) {
        const float* bpr = B + (size_t)((c << 6) + bkr) * ldb + srccol;
        #pragma unroll
        for (int j = 0; j < 4; j++) bv[j] = *(const float4*)(bpr + j * 4);
    };
    auto sts_b = [&](char* stg) {
        char* ph = stg + 16384 + (bq >> 2) * 8192;
        uint32_t o = (uint32_t)(bkr * 128 + (bq & 3) * 32);
        uint2 a0 = hround4(bv[0]), a1 = hround4(bv[1]);
        uint2 a2 = hround4(bv[2]), a3 = hround4(bv[3]);
        *(uint4*)(ph + SWZ(o))      = make_uint4(a0.x, a0.y, a1.x, a1.y);
        *(uint4*)(ph + SWZ(o + 16)) = make_uint4(a2.x, a2.y, a3.x, a3.y);
    };

    cp_a(0);
    ldg_b(0);
    sts_b(dsm);
    CP_WAIT0();
    __syncthreads();

    for (int c = 0; c < NCH; c++) {
        if (c + 1 < NCH) { cp_a(c + 1); ldg_b(c + 1); }
        mma_chunk(smem_u32(dsm + (c & 1) * STAGE_BYTES), wm, wn, lane, F);
        if (c + 1 < NCH) { sts_b(dsm + ((c + 1) & 1) * STAGE_BYTES); CP_WAIT0(); }
        __syncthreads();
    }

    // ---- epilogue: accum -> smem fp32, silu(g)*u -> fp16 -> gmem
    float* ep = (float*)dsm;
    stage_accum(ep, wm, wn, lane, F);
    __syncthreads();

    int m = tid >> 2, seg = tid & 3;
    int rg = m0 + m;
    if (rg < rows) {
        unsigned short* Oh = routed ? g_act16 : g_sact16;
        size_t rowoff = ((size_t)(routed ? e * CAP : 0) + rg) * Ihalf + cb + seg * 16;
        const float* gp = ep + m * 128 + seg * 16;
        const float* up = gp + 64;
        uint32_t hi[8];
        #pragma unroll
        for (int j = 0; j < 8; j++) {
            float g0 = gp[2*j],   u0 = up[2*j];
            float g1 = gp[2*j+1], u1 = up[2*j+1];
            float s0 = u0 * g0 / (1.f + expf(-g0));
            float s1 = u1 * g1 / (1.f + expf(-g1));
            hi[j] = pack2(__half_as_ushort(__float2half_rn(s0)),
                          __half_as_ushort(__float2half_rn(s1)));
        }
        #pragma unroll
        for (int j = 0; j < 2; j++)
            *(uint4*)(Oh + rowoff + j * 8) = *(uint4*)(hi + j * 4);
    }
}

// =======================================================================
// merged down GEMM: acts fp16 via cp.async @ W(fp16-rounded) -> fp32
// =======================================================================
__global__ void __launch_bounds__(NT, 1)
k_mma_down(const float* __restrict__ Wd, const float* __restrict__ Wsd,
           float* __restrict__ Oext)
{
    extern __shared__ char dsm[];
    int bid = blockIdx.x;
    int routed, e, mt, bx, Kdim, cap;
    const float* B;
    if (bid < DN_SH_CTAS) {
        routed = 0; Kdim = IS; cap = T_TOK;
        bx = bid % (HID / 128); mt = bid / (HID / 128); e = 0;
        B = Wsd;
    } else {
        bid -= DN_SH_CTAS;
        routed = 1; Kdim = IR; cap = CAP;
        bx = bid % (HID / 128); int by = bid / (HID / 128);
        e = by / (CAP / 128); mt = by % (CAP / 128);
        B = Wd + (size_t)e * IR * HID;
    }
    int tid = threadIdx.x, wid = tid >> 5, lane = tid & 31;
    int wm = wid & 3, wn = wid >> 2;
    int n0 = bx * 128;
    int rows = routed ? min(g_cnt[e], cap) : cap;
    int m0 = mt * 128;
    if (m0 >= rows) return;

    const unsigned short* Ah = routed ? g_act16 : g_sact16;
    size_t abase = ((size_t)(routed ? e * CAP : 0) + m0) * Kdim;
    const int NCH = Kdim >> 6;

    float F[2][4][4];
    #pragma unroll
    for (int mi = 0; mi < 2; mi++)
        #pragma unroll
        for (int ni = 0; ni < 4; ni++)
            #pragma unroll
            for (int q = 0; q < 4; q++) F[mi][ni][q] = 0.f;

    int arow = tid >> 2, aq = tid & 3;
    int bkr = tid >> 3, bq = tid & 7;
    float4 bv[4];

    auto cp_a = [&](int c) {
        char* stg = dsm + (c & 1) * STAGE_BYTES;
        uint32_t sb = smem_u32(stg);
        size_t off = abase + (size_t)arow * Kdim + (c << 6) + aq * 16;
        uint32_t o = arow * 128 + aq * 32;
        CP_ASYNC16(sb + SWZ(o),      Ah + off);
        CP_ASYNC16(sb + SWZ(o + 16), Ah + off + 8);
        CP_COMMIT();
    };
    auto ldg_b = [&](int c) {
        const float* bpr = B + (size_t)((c << 6) + bkr) * HID + n0 + bq * 16;
        #pragma unroll
        for (int j = 0; j < 4; j++) bv[j] = *(const float4*)(bpr + j * 4);
    };
    auto sts_b = [&](char* stg) {
        char* ph = stg + 16384 + (bq >> 2) * 8192;
        uint32_t o = (uint32_t)(bkr * 128 + (bq & 3) * 32);
        uint2 a0 = hround4(bv[0]), a1 = hround4(bv[1]);
        uint2 a2 = hround4(bv[2]), a3 = hround4(bv[3]);
        *(uint4*)(ph + SWZ(o))      = make_uint4(a0.x, a0.y, a1.x, a1.y);
        *(uint4*)(ph + SWZ(o + 16)) = make_uint4(a2.x, a2.y, a3.x, a3.y);
    };

    cp_a(0);
    ldg_b(0);
    sts_b(dsm);
    CP_WAIT0();
    __syncthreads();

    for (int c = 0; c < NCH; c++) {
        if (c + 1 < NCH) { cp_a(c + 1); ldg_b(c + 1); }
        mma_chunk(smem_u32(dsm + (c & 1) * STAGE_BYTES), wm, wn, lane, F);
        if (c + 1 < NCH) { sts_b(dsm + ((c + 1) & 1) * STAGE_BYTES); CP_WAIT0(); }
        __syncthreads();
    }

    float* ep = (float*)dsm;
    stage_accum(ep, wm, wn, lane, F);
    __syncthreads();

    int m = tid >> 2, cs = (tid & 3) << 5;
    int rg = m0 + m;
    if (rg < rows) {
        float* O = routed ? g_y : Oext;
        float* op = O + ((size_t)(routed ? e * CAP : 0) + rg) * HID + n0 + cs;
        const float* sp = ep + m * 128 + cs;
        #pragma unroll
        for (int j = 0; j < 8; j++)
            *(float4*)(op + j * 4) = *(const float4*)(sp + j * 4);
    }
}

// ---------------- combine ----------------
__global__ void k_combine(float* __restrict__ out) {
    int idx = blockIdx.x * 256 + threadIdx.x;
    int t = idx >> 9;
    int h = (idx & 511) << 2;
    float* op = out + (size_t)t * HID + h;
    float4 acc = *(float4*)op;
    #pragma unroll
    for (int k = 0; k < TOPK; k++) {
        int s = g_slot[t * TOPK + k];
        if (s >= 0) {
            float wv = g_topk_w[t * TOPK + k];
            float4 y = *(const float4*)(g_y + (size_t)s * HID + h);
            acc.x += wv * y.x; acc.y += wv * y.y; acc.z += wv * y.z; acc.w += wv * y.w;
        }
    }
    *(float4*)op = acc;
}

// ---------------- entry ----------------
extern "C" void kernel_launch(void* const* d_in, const int* in_sizes, int n_in,
                              void* d_out, int out_size) {
    const float* x    = (const float*)d_in[0];
    const float* gw   = (const float*)d_in[1];
    const float* wgu  = (const float*)d_in[2];
    const float* wd   = (const float*)d_in[3];
    const float* wsgu = (const float*)d_in[4];
    const float* wsd  = (const float*)d_in[5];
    float* out = (float*)d_out;

    cudaFuncSetAttribute(k_mma_gateup, cudaFuncAttributeMaxDynamicSharedMemorySize, SMEM_DYN);
    cudaFuncSetAttribute(k_mma_down,   cudaFuncAttributeMaxDynamicSharedMemorySize, SMEM_DYN);

    k_convx   <<<(T_TOK * HID / 4) / 256, 256>>>(x);
    k_gate    <<<T_TOK, 256>>>(x, gw);
    k_dispatch<<<1, 1024>>>();
    k_mma_gateup<<<GU_SH_CTAS + GU_RT_CTAS, NT, SMEM_DYN>>>(wgu, wsgu);
    k_mma_down  <<<DN_SH_CTAS + DN_RT_CTAS, NT, SMEM_DYN>>>(wd, wsd, out);
    k_combine <<<(T_TOK * HID / 4) / 256, 256>>>(out);
}